// round 1
// baseline (speedup 1.0000x reference)
#include <cuda_runtime.h>

// Elman RNN, persistent-kernel formulation.
// grid = 128 CTAs: p = blockIdx>>6 picks batch half (128 rows), q = blockIdx&63
// picks 8 output columns. Each CTA keeps its [Wh;Wx] column slice in smem for
// the whole run. Recurrent state ping-pongs through __device__ global memory
// with .cg loads/stores (L1 is not coherent across SMs). One two-level atomic
// grid barrier per timestep.

#define NCTA 128
#define TPB  256

#define Bb 256
#define Tt 512
#define Ff 256
#define Hh 512
#define KTOT 768          // Hh + Ff (fused K: recurrent part then input part)
#define NTILE 24          // KTOT / 32
#define KTILE 32
#define MROWS 128         // batch rows per group
#define SA_STRIDE 36      // padded row stride (floats) for the A tile

__device__ float    g_h[2][Bb * Hh];   // ping-pong hidden state, zero-init by CUDA
__device__ unsigned g_cnt[8 * 64];     // 8 arrival cells, 256B apart
__device__ unsigned g_master;
__device__ unsigned g_gen;
__device__ unsigned g_exit;

__device__ __forceinline__ void grid_barrier(int bar) {
    __syncthreads();
    if (threadIdx.x == 0) {
        __threadfence();
        unsigned cell = blockIdx.x & 7u;
        unsigned prev = atomicAdd(&g_cnt[cell * 64], 1u);
        if (prev == 16u * (unsigned)(bar + 1) - 1u) {        // last in cell
            unsigned m = atomicAdd(&g_master, 1u);
            if (m == 8u * (unsigned)(bar + 1) - 1u) {        // last cell
                atomicExch(&g_gen, (unsigned)(bar + 1));     // release
            }
        }
        while (*((volatile unsigned*)&g_gen) < (unsigned)(bar + 1)) { }
        __threadfence();
    }
    __syncthreads();
}

__global__ void __launch_bounds__(TPB, 1)
rnn_persistent(const float* __restrict__ x,
               const float* __restrict__ Wx,
               const float* __restrict__ Wh,
               const float* __restrict__ bias,
               const float* __restrict__ Wfc,
               const float* __restrict__ bfc,
               float* __restrict__ out)
{
    __shared__ float sW[KTOT * 8];          // 24 KB: resident weight slice
    __shared__ float sA[MROWS * SA_STRIDE]; // 18 KB: A tile [128 x 32], padded

    const int tid = threadIdx.x;
    const int p   = blockIdx.x >> 6;   // batch half
    const int q   = blockIdx.x & 63;   // column tile
    const int q8  = q << 3;

    // Load the persistent weight slice: rows 0..511 = Wh[:, q8..q8+7],
    // rows 512..767 = Wx[:, q8..q8+7].
    for (int i = tid; i < KTOT * 8; i += TPB) {
        int kr = i >> 3, c = i & 7;
        sW[i] = (kr < Hh) ? Wh[kr * Hh + q8 + c]
                          : Wx[(kr - Hh) * Hh + q8 + c];
    }

    // Compute-thread mapping: r = row (0..127), cc = which float4 of the 8 cols.
    const int cc = tid & 1;
    const int r  = tid >> 1;
    // Load-thread mapping: rows r0, r0+32, r0+64, r0+96; c4 = float4 column.
    const int r0 = tid >> 3;
    const int c4 = tid & 7;

    const float4  bb   = ((const float4*)bias)[q * 2 + cc];
    const float4* sW4  = (const float4*)sW;
    const float2* hrow = (const float2*)&sA[r * SA_STRIDE];

    __syncthreads();

    for (int t = 0; t < Tt; ++t) {
        const int cur = t & 1;      // read buffer (t==0 reads nothing: h0 == 0)
        const int nxt = cur ^ 1;    // write buffer
        const int kt0 = (t == 0) ? 16 : 0;

        float4 acc = make_float4(0.f, 0.f, 0.f, 0.f);
        float4 ra[4];

        // Prefetch first tile into registers.
        {
            const int kt = kt0;
            if (kt < 16) {
                const float4* src = (const float4*)g_h[cur];
                #pragma unroll
                for (int i = 0; i < 4; i++) {
                    int rr = r0 + 32 * i;
                    ra[i] = __ldcg(&src[(p * MROWS + rr) * (Hh / 4) + kt * 8 + c4]);
                }
            } else {
                const float4* src = (const float4*)x;
                #pragma unroll
                for (int i = 0; i < 4; i++) {
                    int rr = r0 + 32 * i;
                    ra[i] = __ldg(&src[((p * MROWS + rr) * Tt + t) * (Ff / 4)
                                       + (kt - 16) * 8 + c4]);
                }
            }
        }

        for (int kt = kt0; kt < NTILE; ++kt) {
            // Stage current tile to smem.
            #pragma unroll
            for (int i = 0; i < 4; i++) {
                *(float4*)&sA[(r0 + 32 * i) * SA_STRIDE + c4 * 4] = ra[i];
            }
            __syncthreads();

            // Prefetch next tile (LDG latency overlaps compute below).
            if (kt + 1 < NTILE) {
                const int kn = kt + 1;
                if (kn < 16) {
                    const float4* src = (const float4*)g_h[cur];
                    #pragma unroll
                    for (int i = 0; i < 4; i++) {
                        int rr = r0 + 32 * i;
                        ra[i] = __ldcg(&src[(p * MROWS + rr) * (Hh / 4) + kn * 8 + c4]);
                    }
                } else {
                    const float4* src = (const float4*)x;
                    #pragma unroll
                    for (int i = 0; i < 4; i++) {
                        int rr = r0 + 32 * i;
                        ra[i] = __ldg(&src[((p * MROWS + rr) * Tt + t) * (Ff / 4)
                                           + (kn - 16) * 8 + c4]);
                    }
                }
            }

            // Compute: acc[0..3] += A[r, k] * W[k, cc*4..cc*4+3], k over this tile.
            {
                const int wbase = kt * 64 + cc;
                #pragma unroll
                for (int kk2 = 0; kk2 < 16; kk2++) {
                    float2 h2 = hrow[kk2];
                    float4 w0 = sW4[wbase + 4 * kk2];
                    float4 w1 = sW4[wbase + 4 * kk2 + 2];
                    acc.x = fmaf(h2.x, w0.x, acc.x);
                    acc.y = fmaf(h2.x, w0.y, acc.y);
                    acc.z = fmaf(h2.x, w0.z, acc.z);
                    acc.w = fmaf(h2.x, w0.w, acc.w);
                    acc.x = fmaf(h2.y, w1.x, acc.x);
                    acc.y = fmaf(h2.y, w1.y, acc.y);
                    acc.z = fmaf(h2.y, w1.z, acc.z);
                    acc.w = fmaf(h2.y, w1.w, acc.w);
                }
            }
            __syncthreads();
        }

        // Epilogue: bias + tanh, write next hidden state (L2-coherent store).
        float4 hn;
        hn.x = tanhf(acc.x + bb.x);
        hn.y = tanhf(acc.y + bb.y);
        hn.z = tanhf(acc.z + bb.z);
        hn.w = tanhf(acc.w + bb.w);
        __stcg(&((float4*)g_h[nxt])[(p * MROWS + r) * (Hh / 4) + q * 2 + cc], hn);

        grid_barrier(t);
    }

    // Final Dense(1): s[b] = h_last[b,:] . Wfc + bfc - LAMBDA_G*RT.
    // h_last lives in g_h[0] (512 steps -> last write was to buffer 0).
    if (blockIdx.x < 8) {
        const int brow = blockIdx.x * 32 + (tid >> 3);
        const int l    = tid & 7;
        float s = 0.f;
        const float* hr = &g_h[0][brow * Hh];
        for (int k = l; k < Hh; k += 8)
            s += __ldcg(&hr[k]) * __ldg(&Wfc[k]);
        s += __shfl_down_sync(0xffffffffu, s, 4, 8);
        s += __shfl_down_sync(0xffffffffu, s, 2, 8);
        s += __shfl_down_sync(0xffffffffu, s, 1, 8);
        if (l == 0) out[brow] = s + __ldg(bfc) - 0.05f;
    }

    // Exit barrier: last CTA resets barrier state so graph replays start clean.
    __syncthreads();
    if (tid == 0) {
        __threadfence();
        unsigned e = atomicAdd(&g_exit, 1u);
        if (e == (unsigned)(NCTA - 1)) {
            #pragma unroll
            for (int i = 0; i < 8; i++) g_cnt[i * 64] = 0u;
            g_master = 0u;
            g_gen    = 0u;
            g_exit   = 0u;
            __threadfence();
        }
    }
}

extern "C" void kernel_launch(void* const* d_in, const int* in_sizes, int n_in,
                              void* d_out, int out_size) {
    const float* x   = (const float*)d_in[0];
    const float* Wx  = (const float*)d_in[1];
    const float* Wh  = (const float*)d_in[2];
    const float* b   = (const float*)d_in[3];
    const float* Wfc = (const float*)d_in[4];
    const float* bfc = (const float*)d_in[5];
    float* out = (float*)d_out;
    (void)in_sizes; (void)n_in; (void)out_size;
    rnn_persistent<<<NCTA, TPB>>>(x, Wx, Wh, b, Wfc, bfc, out);
}